// round 8
// baseline (speedup 1.0000x reference)
#include <cuda_runtime.h>
#include <math.h>
#include <stdint.h>

// ---------------------------------------------------------------------------
// Problem constants
// ---------------------------------------------------------------------------
#define HID    4096
#define SEQ    2048
#define BATCH  2
#define NHEADS 32
#define NKV    8
#define HD     128
#define KVW    (NKV * HD)        // 1024
#define MROWS  (BATCH * SEQ)     // 4096

// ---------------------------------------------------------------------------
// Scratch (device globals: no allocation allowed)
// ---------------------------------------------------------------------------
__device__ float g_Q[(size_t)MROWS * HID];
__device__ float g_K[(size_t)MROWS * KVW];
__device__ float g_V[(size_t)MROWS * KVW];
__device__ float g_A[(size_t)MROWS * HID];
__device__ float g_X[(size_t)MROWS * HID];
__device__ float g_Wq[(size_t)HID * HID];
__device__ float g_Wk[(size_t)HID * KVW];
__device__ float g_Wv[(size_t)HID * KVW];
__device__ float g_Wo[(size_t)HID * HID];

// ---------------------------------------------------------------------------
// tf32 helpers
// ---------------------------------------------------------------------------
__device__ __forceinline__ float to_tf32(float x) {
    uint32_t r;
    asm("cvt.rna.tf32.f32 %0, %1;" : "=r"(r) : "f"(x));
    return __uint_as_float(r);
}
__device__ __forceinline__ uint32_t fau(float x) { return __float_as_uint(x); }

__global__ void round_tf32_kernel(const float* __restrict__ in,
                                  float* __restrict__ out, int n4)
{
    int i = blockIdx.x * blockDim.x + threadIdx.x;
    if (i >= n4) return;
    float4 v = ((const float4*)in)[i];
    v.x = to_tf32(v.x); v.y = to_tf32(v.y);
    v.z = to_tf32(v.z); v.w = to_tf32(v.w);
    ((float4*)out)[i] = v;
}

// fast exp2 on the fma/alu pipes
__device__ __forceinline__ float exp2p(float x) {
    x = fmaxf(x, -126.f);
    float t = x + 12582912.f;
    float n = t - 12582912.f;
    float f = x - n;
    float p = 1.5403530e-4f;
    p = fmaf(p, f, 1.3333558e-3f);
    p = fmaf(p, f, 9.6181291e-3f);
    p = fmaf(p, f, 5.5504109e-2f);
    p = fmaf(p, f, 2.4022651e-1f);
    p = fmaf(p, f, 6.9314718e-1f);
    p = fmaf(p, f, 1.0f);
    float sc = __int_as_float(0x3f800000 + (__float_as_int(t) << 23));
    return p * sc;
}

__device__ __forceinline__ void mma_tf32(float* c, uint32_t a0, uint32_t a1,
                                         uint32_t a2, uint32_t a3,
                                         uint32_t b0, uint32_t b1)
{
    asm volatile(
        "mma.sync.aligned.m16n8k8.row.col.f32.tf32.tf32.f32 "
        "{%0,%1,%2,%3}, {%4,%5,%6,%7}, {%8,%9}, {%0,%1,%2,%3};\n"
        : "+f"(c[0]), "+f"(c[1]), "+f"(c[2]), "+f"(c[3])
        : "r"(a0), "r"(a1), "r"(a2), "r"(a3), "r"(b0), "r"(b1));
}

__device__ __forceinline__ void cp16(uint32_t dst, const float* src) {
    asm volatile("cp.async.cg.shared.global [%0], [%1], 16;\n"
                 :: "r"(dst), "l"(src));
}
#define CP_COMMIT() asm volatile("cp.async.commit_group;\n" ::: "memory")
#define CP_WAIT1()  asm volatile("cp.async.wait_group 1;\n" ::: "memory")
#define CP_WAIT0()  asm volatile("cp.async.wait_group 0;\n" ::: "memory")

// ---------------------------------------------------------------------------
// TF32 tensor-core GEMM (proven config):
// 128x128x32 tile, 128 threads (2x2 warps), 2 CTAs/SM, 2-stage cp.async.
// ---------------------------------------------------------------------------
#define BM 128
#define BN 128
#define BK 32
#define AST 36
#define BST 136
#define GEMM_SMEM ((2 * BM * AST + 2 * BK * BST) * 4)   // 71680 B

__global__ void __launch_bounds__(128, 2)
tf32gemm(const float* __restrict__ A, const float* __restrict__ B,
         float* __restrict__ C, int M, int N, int K, int round_out)
{
    extern __shared__ float sm[];
    float* As = sm;
    float* Bs = sm + 2 * BM * AST;

    const int tid  = threadIdx.x;
    const int warp = tid >> 5;
    const int lane = tid & 31;
    const int wm = warp >> 1;
    const int wn = warp & 1;
    const int g  = lane >> 2;
    const int tg = lane & 3;
    const int bm = blockIdx.y * BM;
    const int bn = blockIdx.x * BN;

    float acc[4][8][4];
#pragma unroll
    for (int mi = 0; mi < 4; mi++)
#pragma unroll
        for (int ni = 0; ni < 8; ni++)
#pragma unroll
            for (int r = 0; r < 4; r++) acc[mi][ni][r] = 0.f;

    const int T = K / BK;

    auto issue = [&](int t, int buf) {
        const float* Ag = A + (size_t)bm * K + t * BK;
#pragma unroll
        for (int u = 0; u < 8; u++) {
            int i4 = tid + 128 * u;
            int r = i4 >> 3, c4 = i4 & 7;
            uint32_t d = (uint32_t)__cvta_generic_to_shared(
                As + buf * BM * AST + r * AST + c4 * 4);
            cp16(d, Ag + (size_t)r * K + c4 * 4);
        }
        const float* Bg = B + (size_t)(t * BK) * N + bn;
#pragma unroll
        for (int u = 0; u < 8; u++) {
            int i4 = tid + 128 * u;
            int r = i4 >> 5, c4 = i4 & 31;
            uint32_t d = (uint32_t)__cvta_generic_to_shared(
                Bs + buf * BK * BST + r * BST + c4 * 4);
            cp16(d, Bg + (size_t)r * N + c4 * 4);
        }
        CP_COMMIT();
    };

    issue(0, 0);

    int buf = 0;
    for (int t = 0; t < T; t++) {
        if (t + 1 < T) {
            issue(t + 1, buf ^ 1);
            CP_WAIT1();
        } else {
            CP_WAIT0();
        }
        __syncthreads();

        const float* Ab = As + buf * BM * AST;
        const float* Bb = Bs + buf * BK * BST;

#pragma unroll
        for (int ks = 0; ks < 4; ks++) {
            const int kc = ks * 8;
            uint32_t a[4][4], b[8][2];
#pragma unroll
            for (int mi = 0; mi < 4; mi++) {
                int row = wm * 64 + mi * 16 + g;
                a[mi][0] = fau(Ab[row * AST + kc + tg]);
                a[mi][1] = fau(Ab[(row + 8) * AST + kc + tg]);
                a[mi][2] = fau(Ab[row * AST + kc + tg + 4]);
                a[mi][3] = fau(Ab[(row + 8) * AST + kc + tg + 4]);
            }
#pragma unroll
            for (int ni = 0; ni < 8; ni++) {
                int col = wn * 64 + ni * 8 + g;
                b[ni][0] = fau(Bb[(kc + tg) * BST + col]);
                b[ni][1] = fau(Bb[(kc + tg + 4) * BST + col]);
            }
#pragma unroll
            for (int mi = 0; mi < 4; mi++)
#pragma unroll
                for (int ni = 0; ni < 8; ni++)
                    mma_tf32(acc[mi][ni], a[mi][0], a[mi][1], a[mi][2], a[mi][3],
                             b[ni][0], b[ni][1]);
        }
        __syncthreads();
        buf ^= 1;
    }

#pragma unroll
    for (int mi = 0; mi < 4; mi++) {
        int row0 = bm + wm * 64 + mi * 16 + g;
#pragma unroll
        for (int ni = 0; ni < 8; ni++) {
            int col = bn + wn * 64 + ni * 8 + tg * 2;
            float4 v = make_float4(acc[mi][ni][0], acc[mi][ni][1],
                                   acc[mi][ni][2], acc[mi][ni][3]);
            if (round_out) {
                v.x = to_tf32(v.x); v.y = to_tf32(v.y);
                v.z = to_tf32(v.z); v.w = to_tf32(v.w);
            }
            *(float2*)(C + (size_t)row0 * N + col) = make_float2(v.x, v.y);
            *(float2*)(C + (size_t)(row0 + 8) * N + col) = make_float2(v.z, v.w);
        }
    }
}

// ---------------------------------------------------------------------------
// RoPE (in-place, pair-safe), rounds outputs to tf32.
// ---------------------------------------------------------------------------
__global__ void rope_kernel(float* __restrict__ T, const int* __restrict__ pos_ids,
                            int cols, int npairs)
{
    int idx = blockIdx.x * blockDim.x + threadIdx.x;
    if (idx >= npairs) return;
    int half = cols >> 1;
    int row = idx / half;
    int cp = idx - row * half;
    int h = cp >> 6;
    int d = cp & 63;
    int c0 = h * 128 + d;
    float pos = (float)pos_ids[row];
    double inv = pow(10000.0, -((double)d) / 64.0);
    float ang = (float)((double)pos * inv);
    float sn = sinf(ang), cs = cosf(ang);
    float* rowp = T + (size_t)row * cols;
    float x0 = rowp[c0];
    float x1 = rowp[c0 + 64];
    rowp[c0]      = to_tf32(x0 * cs - x1 * sn);
    rowp[c0 + 64] = to_tf32(x1 * cs + x0 * sn);
}

// ---------------------------------------------------------------------------
// Tensor-core flash attention (causal, GQA), tf32 mma.sync.
// CTA = 64 q rows x head x batch; 4 warps x 16 rows; K-tile 32, 2-stage.
// Small CTA (100.3 KB smem, 128 thr) -> 2 CTAs/SM: one CTA's mma covers the
// other's softmax/barrier latency. Q frags in regs; Q smem reused for P.
// ---------------------------------------------------------------------------
#define FQ   64
#define FKT  32
#define QST  132   // %32==4 -> conflict-free Q fragment extraction
#define KST  132   // %32==4 -> K^T b-frag conflict-free
#define VST  136   // %32==8 -> V b-frag conflict-free
#define PST2 36    // %32==4 -> P a-frag conflict-free

#define OFF_K  0
#define OFF_V  (OFF_K + 2 * FKT * KST)          // 8448
#define OFF_QP (OFF_V + 2 * FKT * VST)          // Q tile first, later P
#define OFF_M  (OFF_QP + FQ * QST)              // 2 x FKT mask biases
#define FL_SMEM ((OFF_M + 2 * FKT) * 4)         // 102656 B

#define SCL 0.12751743f   // (1/sqrt(128)) * log2(e)

__global__ void __launch_bounds__(128, 2)
flash_tc(const float* __restrict__ Q, const float* __restrict__ K,
         const float* __restrict__ V, const float* __restrict__ amask,
         float* __restrict__ Oc)
{
    extern __shared__ float sm[];
    float* Ks  = sm + OFF_K;
    float* Vs  = sm + OFF_V;
    float* QPs = sm + OFF_QP;     // Q during prologue, P during mainloop
    float* kmb = sm + OFF_M;

    const int hb = blockIdx.x;
    const int h = hb & 31, b = hb >> 5;
    const int qb = gridDim.y - 1 - blockIdx.y;     // heavy q-blocks first
    const int q0 = qb * FQ;
    const int tid = threadIdx.x;
    const int w = tid >> 5, lane = tid & 31;
    const int g = lane >> 2, tg = lane & 3;
    const int kvh = h >> 2;
    const int myrowmax = q0 + w * 16 + 15;

    float oacc[16][4];
#pragma unroll
    for (int nt = 0; nt < 16; nt++)
#pragma unroll
        for (int r = 0; r < 4; r++) oacc[nt][r] = 0.f;
    float m2[2] = {-1e9f, -1e9f}, l2[2] = {0.f, 0.f};

    // async K/V/mask tile loader (32 x 128 each)
    auto issue = [&](int t, int buf) {
        const float* Kg = K + (size_t)(b * SEQ + t * FKT) * KVW + kvh * HD;
        const float* Vg = V + (size_t)(b * SEQ + t * FKT) * KVW + kvh * HD;
#pragma unroll
        for (int u = 0; u < 8; u++) {
            int i4 = tid + 128 * u;
            int r = i4 >> 5, c4 = i4 & 31;
            uint32_t dk = (uint32_t)__cvta_generic_to_shared(
                Ks + buf * FKT * KST + r * KST + c4 * 4);
            cp16(dk, Kg + (size_t)r * KVW + c4 * 4);
            uint32_t dv = (uint32_t)__cvta_generic_to_shared(
                Vs + buf * FKT * VST + r * VST + c4 * 4);
            cp16(dv, Vg + (size_t)r * KVW + c4 * 4);
        }
        if (tid < FKT)
            kmb[buf * FKT + tid] =
                (amask[b * SEQ + t * FKT + tid] > 0.f) ? 0.f : -1e9f;
        CP_COMMIT();
    };

    issue(0, 0);     // overlap with Q staging

    // Q tile -> smem (plain stores): 64 x 128 = 2048 float4
    const float* Qg = Q + (size_t)(b * SEQ + q0) * HID + h * HD;
#pragma unroll
    for (int u = 0; u < 16; u++) {
        int i4 = tid + 128 * u;
        int r = i4 >> 5, c4 = i4 & 31;
        float4 v = *(const float4*)(Qg + (size_t)r * HID + c4 * 4);
        QPs[r * QST + c4 * 4 + 0] = v.x;
        QPs[r * QST + c4 * 4 + 1] = v.y;
        QPs[r * QST + c4 * 4 + 2] = v.z;
        QPs[r * QST + c4 * 4 + 3] = v.w;
    }
    __syncthreads();               // Q visible

    // Q fragments -> registers (64 regs)
    uint32_t qa[16][4];
    {
        const float* Qw = QPs + (w * 16) * QST;
#pragma unroll
        for (int ks = 0; ks < 16; ks++) {
            const int kc = ks * 8;
            qa[ks][0] = fau(Qw[g * QST + kc + tg]);
            qa[ks][1] = fau(Qw[(g + 8) * QST + kc + tg]);
            qa[ks][2] = fau(Qw[g * QST + kc + tg + 4]);
            qa[ks][3] = fau(Qw[(g + 8) * QST + kc + tg + 4]);
        }
    }
    __syncthreads();               // Q reads done -> region becomes P

    const int T = 2 * (qb + 1);
    float* Pw = QPs + (w * 16) * PST2;

    for (int t = 0; t < T; t++) {
        const int buf = t & 1;
        if (t + 1 < T) {
            issue(t + 1, buf ^ 1);
            CP_WAIT1();
        } else {
            CP_WAIT0();
        }
        __syncthreads();                         // tile t visible everywhere

        const int k0 = t * FKT;
        if (k0 <= myrowmax) {                    // else fully masked for warp

            // ---- S = Q @ K^T (16 x 32 per warp) ----
            float sacc[4][4];
#pragma unroll
            for (int nt = 0; nt < 4; nt++)
#pragma unroll
                for (int r = 0; r < 4; r++) sacc[nt][r] = 0.f;

            const float* Kb = Ks + buf * FKT * KST;
#pragma unroll
            for (int ks = 0; ks < 16; ks++) {
                const int kc = ks * 8;
#pragma unroll
                for (int nt = 0; nt < 4; nt++) {
                    uint32_t b0 = fau(Kb[(nt * 8 + g) * KST + kc + tg]);
                    uint32_t b1 = fau(Kb[(nt * 8 + g) * KST + kc + tg + 4]);
                    mma_tf32(sacc[nt], qa[ks][0], qa[ks][1], qa[ks][2],
                             qa[ks][3], b0, b1);
                }
            }

            // ---- mask + scale into exp2 domain ----
            const int rowg0 = q0 + w * 16 + g;
            const int rowg1 = rowg0 + 8;
#pragma unroll
            for (int nt = 0; nt < 4; nt++) {
                int cl = nt * 8 + 2 * tg;
                int c0 = k0 + cl;
                float kb0 = kmb[buf * FKT + cl];
                float kb1 = kmb[buf * FKT + cl + 1];
                sacc[nt][0] = (c0     <= rowg0) ? sacc[nt][0] * SCL + kb0 : -1e9f;
                sacc[nt][1] = (c0 + 1 <= rowg0) ? sacc[nt][1] * SCL + kb1 : -1e9f;
                sacc[nt][2] = (c0     <= rowg1) ? sacc[nt][2] * SCL + kb0 : -1e9f;
                sacc[nt][3] = (c0 + 1 <= rowg1) ? sacc[nt][3] * SCL + kb1 : -1e9f;
            }

            // ---- online softmax (exp2 domain) ----
#pragma unroll
            for (int r = 0; r < 2; r++) {
                float pm = -1e30f;
#pragma unroll
                for (int nt = 0; nt < 4; nt++)
                    pm = fmaxf(pm, fmaxf(sacc[nt][2 * r], sacc[nt][2 * r + 1]));
                pm = fmaxf(pm, __shfl_xor_sync(0xffffffffu, pm, 1));
                pm = fmaxf(pm, __shfl_xor_sync(0xffffffffu, pm, 2));
                float mn = fmaxf(m2[r], pm);
                float al = exp2p(m2[r] - mn);
                m2[r] = mn;
                float rs = 0.f;
                float* prow = QPs + (w * 16 + g + 8 * r) * PST2;
#pragma unroll
                for (int nt = 0; nt < 4; nt++) {
                    float p0 = exp2p(sacc[nt][2 * r] - mn);
                    float p1 = exp2p(sacc[nt][2 * r + 1] - mn);
                    rs += p0 + p1;
                    *(float2*)(prow + nt * 8 + 2 * tg) =
                        make_float2(to_tf32(p0), to_tf32(p1));
                }
                rs += __shfl_xor_sync(0xffffffffu, rs, 1);
                rs += __shfl_xor_sync(0xffffffffu, rs, 2);
                l2[r] = l2[r] * al + rs;
                if (al != 1.f) {
#pragma unroll
                    for (int nt = 0; nt < 16; nt++) {
                        oacc[nt][2 * r]     *= al;
                        oacc[nt][2 * r + 1] *= al;
                    }
                }
            }
            __syncwarp();

            // ---- O += P @ V ----
            const float* Vb = Vs + buf * FKT * VST;
#pragma unroll
            for (int ks = 0; ks < 4; ks++) {
                const int kc = ks * 8;
                uint32_t a0 = fau(Pw[g * PST2 + kc + tg]);
                uint32_t a1 = fau(Pw[(g + 8) * PST2 + kc + tg]);
                uint32_t a2 = fau(Pw[g * PST2 + kc + tg + 4]);
                uint32_t a3 = fau(Pw[(g + 8) * PST2 + kc + tg + 4]);
#pragma unroll
                for (int nt = 0; nt < 16; nt++) {
                    uint32_t b0 = fau(Vb[(kc + tg) * VST + nt * 8 + g]);
                    uint32_t b1 = fau(Vb[(kc + tg + 4) * VST + nt * 8 + g]);
                    mma_tf32(oacc[nt], a0, a1, a2, a3, b0, b1);
                }
            }
        }
        __syncthreads();                         // all reads of buf done
    }

    // ---- epilogue ----
    float i0 = 1.f / l2[0], i1 = 1.f / l2[1];
    size_t ro0 = (size_t)(b * SEQ + q0 + w * 16 + g) * HID + h * HD;
    size_t ro1 = ro0 + (size_t)8 * HID;
#pragma unroll
    for (int nt = 0; nt < 16; nt++) {
        int c = nt * 8 + 2 * tg;
        *(float2*)(Oc + ro0 + c) = make_float2(to_tf32(oacc[nt][0] * i0),
                                               to_tf32(oacc[nt][1] * i0));
        *(float2*)(Oc + ro1 + c) = make_float2(to_tf32(oacc[nt][2] * i1),
                                               to_tf32(oacc[nt][3] * i1));
    }
}

// ---------------------------------------------------------------------------
// Launch
// ---------------------------------------------------------------------------
extern "C" void kernel_launch(void* const* d_in, const int* in_sizes, int n_in,
                              void* d_out, int out_size)
{
    const float* hs    = (const float*)d_in[0];
    const float* amask = (const float*)d_in[1];
    const int*   pos   = (const int*)d_in[2];
    const float* Wq    = (const float*)d_in[3];
    const float* Wk    = (const float*)d_in[4];
    const float* Wv    = (const float*)d_in[5];
    const float* Wo    = (const float*)d_in[6];
    float* out = (float*)d_out;

    float *Qp, *Kp, *Vp, *Ap, *Xp, *Wqp, *Wkp, *Wvp, *Wop;
    cudaGetSymbolAddress((void**)&Qp, g_Q);
    cudaGetSymbolAddress((void**)&Kp, g_K);
    cudaGetSymbolAddress((void**)&Vp, g_V);
    cudaGetSymbolAddress((void**)&Ap, g_A);
    cudaGetSymbolAddress((void**)&Xp, g_X);
    cudaGetSymbolAddress((void**)&Wqp, g_Wq);
    cudaGetSymbolAddress((void**)&Wkp, g_Wk);
    cudaGetSymbolAddress((void**)&Wvp, g_Wv);
    cudaGetSymbolAddress((void**)&Wop, g_Wo);

    cudaFuncSetAttribute(tf32gemm, cudaFuncAttributeMaxDynamicSharedMemorySize,
                         GEMM_SMEM);
    cudaFuncSetAttribute(flash_tc, cudaFuncAttributeMaxDynamicSharedMemorySize,
                         FL_SMEM);

    // Round inputs to tf32 (RNA)
    {
        int n;
        n = MROWS * HID / 4;
        round_tf32_kernel<<<(n + 255) / 256, 256>>>(hs, Xp, n);
        n = HID * HID / 4;
        round_tf32_kernel<<<(n + 255) / 256, 256>>>(Wq, Wqp, n);
        round_tf32_kernel<<<(n + 255) / 256, 256>>>(Wo, Wop, n);
        n = HID * KVW / 4;
        round_tf32_kernel<<<(n + 255) / 256, 256>>>(Wk, Wkp, n);
        round_tf32_kernel<<<(n + 255) / 256, 256>>>(Wv, Wvp, n);
    }

    // Projections (tf32 tensor cores); outputs rounded to tf32
    tf32gemm<<<dim3(HID / BN, MROWS / BM), 128, GEMM_SMEM>>>(Xp, Wqp, Qp, MROWS, HID, HID, 1);
    tf32gemm<<<dim3(KVW / BN, MROWS / BM), 128, GEMM_SMEM>>>(Xp, Wkp, Kp, MROWS, KVW, HID, 1);
    tf32gemm<<<dim3(KVW / BN, MROWS / BM), 128, GEMM_SMEM>>>(Xp, Wvp, Vp, MROWS, KVW, HID, 1);

    // RoPE on Q and K
    {
        int npq = MROWS * (HID / 2);
        rope_kernel<<<(npq + 255) / 256, 256>>>(Qp, pos, HID, npq);
        int npk = MROWS * (KVW / 2);
        rope_kernel<<<(npk + 255) / 256, 256>>>(Kp, pos, KVW, npk);
    }

    // Tensor-core flash attention (FQ=64, 2 CTAs/SM)
    flash_tc<<<dim3(NHEADS * BATCH, SEQ / FQ), 128, FL_SMEM>>>(Qp, Kp, Vp,
                                                               amask, Ap);

    // Output projection, full fp32 output
    tf32gemm<<<dim3(HID / BN, MROWS / BM), 128, GEMM_SMEM>>>(Ap, Wop, out, MROWS, HID, HID, 0);
}

// round 10
// speedup vs baseline: 1.7278x; 1.7278x over previous
#include <cuda_runtime.h>
#include <cuda_fp16.h>
#include <math.h>
#include <stdint.h>

// ---------------------------------------------------------------------------
// Problem constants
// ---------------------------------------------------------------------------
#define HID    4096
#define SEQ    2048
#define BATCH  2
#define NHEADS 32
#define NKV    8
#define HD     128
#define KVW    (NKV * HD)        // 1024
#define MROWS  (BATCH * SEQ)     // 4096

// ---------------------------------------------------------------------------
// Scratch (device globals: no allocation allowed) — fp16 operands
// ---------------------------------------------------------------------------
__device__ __half g_X [(size_t)MROWS * HID];
__device__ __half g_Wq[(size_t)HID * HID];    // transposed [N][K]
__device__ __half g_Wk[(size_t)HID * KVW];
__device__ __half g_Wv[(size_t)HID * KVW];
__device__ __half g_Wo[(size_t)HID * HID];
__device__ __half g_Q [(size_t)MROWS * HID];
__device__ __half g_K [(size_t)MROWS * KVW];
__device__ __half g_V [(size_t)MROWS * KVW];
__device__ __half g_Vt[(size_t)MROWS * KVW];  // [b*8+kvh][d][seq]
__device__ __half g_A [(size_t)MROWS * HID];

// ---------------------------------------------------------------------------
// helpers
// ---------------------------------------------------------------------------
__device__ __forceinline__ uint32_t fau(float x) { return __float_as_uint(x); }

// convert fp32 -> fp16 (vectorized)
__global__ void f2h_kernel(const float* __restrict__ in,
                           __half* __restrict__ out, int n4)
{
    int i = blockIdx.x * blockDim.x + threadIdx.x;
    if (i >= n4) return;
    float4 v = ((const float4*)in)[i];
    __half2* o = (__half2*)(out + 4 * (size_t)i);
    o[0] = __floats2half2_rn(v.x, v.y);
    o[1] = __floats2half2_rn(v.z, v.w);
}

// transpose + convert: out[n][k] = half(in[k][n])
__global__ void transpose_h(const float* __restrict__ in,
                            __half* __restrict__ out, int K, int N)
{
    __shared__ float t[32][33];
    int k0 = blockIdx.y * 32, n0 = blockIdx.x * 32;
    int x = threadIdx.x, y = threadIdx.y;   // 32 x 8
#pragma unroll
    for (int i = 0; i < 32; i += 8)
        t[y + i][x] = in[(size_t)(k0 + y + i) * N + n0 + x];
    __syncthreads();
#pragma unroll
    for (int i = 0; i < 32; i += 8)
        out[(size_t)(n0 + y + i) * K + k0 + x] = __float2half_rn(t[x][y + i]);
}

// V transpose: Vt[b*8+kvh][d][s] = V[(b*SEQ+s)][kvh*128+d]
__global__ void vtrans_kernel(const __half* __restrict__ V,
                              __half* __restrict__ Vt)
{
    __shared__ __half t[32][33];
    int p = blockIdx.z;            // 0..15
    int b = p >> 3, kvh = p & 7;
    int s0 = blockIdx.x * 32, d0 = blockIdx.y * 32;
    int x = threadIdx.x, y = threadIdx.y;   // 32 x 8
#pragma unroll
    for (int i = 0; i < 32; i += 8)
        t[y + i][x] = V[(size_t)(b * SEQ + s0 + y + i) * KVW + kvh * 128 + d0 + x];
    __syncthreads();
#pragma unroll
    for (int i = 0; i < 32; i += 8)
        Vt[((size_t)p * 128 + d0 + y + i) * SEQ + s0 + x] = t[x][y + i];
}

// fast exp2 on the fma/alu pipes
__device__ __forceinline__ float exp2p(float x) {
    x = fmaxf(x, -126.f);
    float t = x + 12582912.f;
    float n = t - 12582912.f;
    float f = x - n;
    float p = 1.5403530e-4f;
    p = fmaf(p, f, 1.3333558e-3f);
    p = fmaf(p, f, 9.6181291e-3f);
    p = fmaf(p, f, 5.5504109e-2f);
    p = fmaf(p, f, 2.4022651e-1f);
    p = fmaf(p, f, 6.9314718e-1f);
    p = fmaf(p, f, 1.0f);
    float sc = __int_as_float(0x3f800000 + (__float_as_int(t) << 23));
    return p * sc;
}

__device__ __forceinline__ void mma_f16(float* c, uint32_t a0, uint32_t a1,
                                        uint32_t a2, uint32_t a3,
                                        uint32_t b0, uint32_t b1)
{
    asm volatile(
        "mma.sync.aligned.m16n8k16.row.col.f32.f16.f16.f32 "
        "{%0,%1,%2,%3}, {%4,%5,%6,%7}, {%8,%9}, {%0,%1,%2,%3};\n"
        : "+f"(c[0]), "+f"(c[1]), "+f"(c[2]), "+f"(c[3])
        : "r"(a0), "r"(a1), "r"(a2), "r"(a3), "r"(b0), "r"(b1));
}

__device__ __forceinline__ void cp16(uint32_t dst, const void* src) {
    asm volatile("cp.async.cg.shared.global [%0], [%1], 16;\n"
                 :: "r"(dst), "l"(src));
}
#define CP_COMMIT() asm volatile("cp.async.commit_group;\n" ::: "memory")
#define CP_WAIT1()  asm volatile("cp.async.wait_group 1;\n" ::: "memory")
#define CP_WAIT0()  asm volatile("cp.async.wait_group 0;\n" ::: "memory")

// ---------------------------------------------------------------------------
// FP16 tensor-core GEMM: C[M,N] = A[M,K] @ Bt[N,K]^T, fp32 accumulate.
// 128x128x64 tile, 128 threads (2x2 warps, 64x64 warp tile), 2 CTAs/SM,
// 2-stage cp.async. Rows padded to 72 halfs (word stride 36 -> 4g+tg banks).
// ---------------------------------------------------------------------------
#define BM 128
#define BN 128
#define BK 64
#define GST2 72                        // halfs per smem row
#define GSTAGE (BM * GST2 * 2)         // 18432 B per tile stage
#define GEMM_SMEM (4 * GSTAGE)         // A x2 + B x2 = 73728 B

__global__ void __launch_bounds__(128, 2)
gemm16(const __half* __restrict__ A, const __half* __restrict__ Bt,
       void* __restrict__ Cv, int M, int N, int K, int half_out)
{
    extern __shared__ char smc[];
    __half* As = (__half*)smc;                       // [2][BM][GST2]
    __half* Bs = (__half*)(smc + 2 * GSTAGE);        // [2][BN][GST2]

    const int tid  = threadIdx.x;
    const int warp = tid >> 5;
    const int lane = tid & 31;
    const int wm = warp >> 1;
    const int wn = warp & 1;
    const int g  = lane >> 2;
    const int tg = lane & 3;
    const int bm = blockIdx.y * BM;
    const int bn = blockIdx.x * BN;

    float acc[4][8][4];
#pragma unroll
    for (int mi = 0; mi < 4; mi++)
#pragma unroll
        for (int ni = 0; ni < 8; ni++)
#pragma unroll
            for (int r = 0; r < 4; r++) acc[mi][ni][r] = 0.f;

    const int T = K / BK;

    auto issue = [&](int t, int s) {
        const __half* Ag = A + (size_t)bm * K + t * BK;
#pragma unroll
        for (int u = 0; u < 8; u++) {              // 128 rows x 8 chunks
            int i = tid + 128 * u;
            int r = i >> 3, c8 = i & 7;
            uint32_t d = (uint32_t)__cvta_generic_to_shared(
                As + s * BM * GST2 + r * GST2 + c8 * 8);
            cp16(d, Ag + (size_t)r * K + c8 * 8);
        }
        const __half* Bg = Bt + (size_t)bn * K + t * BK;
#pragma unroll
        for (int u = 0; u < 8; u++) {
            int i = tid + 128 * u;
            int r = i >> 3, c8 = i & 7;
            uint32_t d = (uint32_t)__cvta_generic_to_shared(
                Bs + s * BN * GST2 + r * GST2 + c8 * 8);
            cp16(d, Bg + (size_t)r * K + c8 * 8);
        }
        CP_COMMIT();
    };

    issue(0, 0);

    int buf = 0;
    for (int t = 0; t < T; t++) {
        if (t + 1 < T) {
            issue(t + 1, buf ^ 1);
            CP_WAIT1();
        } else {
            CP_WAIT0();
        }
        __syncthreads();

        const uint32_t* Aw = (const uint32_t*)(As + buf * BM * GST2);
        const uint32_t* Bw = (const uint32_t*)(Bs + buf * BN * GST2);

#pragma unroll
        for (int ks = 0; ks < 4; ks++) {           // 4 k16 steps
            const int kw = ks * 8;
            uint32_t a[4][4], b[8][2];
#pragma unroll
            for (int mi = 0; mi < 4; mi++) {
                int row = wm * 64 + mi * 16 + g;
                a[mi][0] = Aw[row * 36 + kw + tg];
                a[mi][1] = Aw[(row + 8) * 36 + kw + tg];
                a[mi][2] = Aw[row * 36 + kw + 4 + tg];
                a[mi][3] = Aw[(row + 8) * 36 + kw + 4 + tg];
            }
#pragma unroll
            for (int ni = 0; ni < 8; ni++) {
                int col = wn * 64 + ni * 8 + g;
                b[ni][0] = Bw[col * 36 + kw + tg];
                b[ni][1] = Bw[col * 36 + kw + 4 + tg];
            }
#pragma unroll
            for (int mi = 0; mi < 4; mi++)
#pragma unroll
                for (int ni = 0; ni < 8; ni++)
                    mma_f16(acc[mi][ni], a[mi][0], a[mi][1], a[mi][2], a[mi][3],
                            b[ni][0], b[ni][1]);
        }
        __syncthreads();
        buf ^= 1;
    }

    // epilogue
#pragma unroll
    for (int mi = 0; mi < 4; mi++) {
        int row0 = bm + wm * 64 + mi * 16 + g;
#pragma unroll
        for (int ni = 0; ni < 8; ni++) {
            int col = bn + wn * 64 + ni * 8 + tg * 2;
            if (half_out) {
                __half* Ch = (__half*)Cv;
                *(__half2*)(Ch + (size_t)row0 * N + col) =
                    __floats2half2_rn(acc[mi][ni][0], acc[mi][ni][1]);
                *(__half2*)(Ch + (size_t)(row0 + 8) * N + col) =
                    __floats2half2_rn(acc[mi][ni][2], acc[mi][ni][3]);
            } else {
                float* Cf = (float*)Cv;
                *(float2*)(Cf + (size_t)row0 * N + col) =
                    make_float2(acc[mi][ni][0], acc[mi][ni][1]);
                *(float2*)(Cf + (size_t)(row0 + 8) * N + col) =
                    make_float2(acc[mi][ni][2], acc[mi][ni][3]);
            }
        }
    }
}

// ---------------------------------------------------------------------------
// RoPE (in-place on fp16, pair-safe: thread owns the (d, d+64) pair).
// ---------------------------------------------------------------------------
__global__ void rope_h(__half* __restrict__ T, const int* __restrict__ pos_ids,
                       int cols, int npairs)
{
    int idx = blockIdx.x * blockDim.x + threadIdx.x;
    if (idx >= npairs) return;
    int half_ = cols >> 1;
    int row = idx / half_;
    int cp = idx - row * half_;
    int h = cp >> 6;
    int d = cp & 63;
    int c0 = h * 128 + d;
    float pos = (float)pos_ids[row];
    double inv = pow(10000.0, -((double)d) / 64.0);
    float ang = (float)((double)pos * inv);
    float sn = sinf(ang), cs = cosf(ang);
    __half* rowp = T + (size_t)row * cols;
    float x0 = __half2float(rowp[c0]);
    float x1 = __half2float(rowp[c0 + 64]);
    rowp[c0]      = __float2half_rn(x0 * cs - x1 * sn);
    rowp[c0 + 64] = __float2half_rn(x1 * cs + x0 * sn);
}

// ---------------------------------------------------------------------------
// FP16 tensor-core flash attention (causal, GQA).
// CTA = 128 q rows x head x batch; 8 warps x 16 rows; K-tile 64, 2-stage.
// Q frags in registers; Q smem region reused for P. V consumed transposed.
// ---------------------------------------------------------------------------
#define FQ   128
#define FKT  64
#define QST2 136                  // Q rows: 128 halfs + 8 pad (word stride 68)
#define KST2 136                  // K rows: 128 halfs + pad
#define VST2 72                   // Vt rows: 64 halfs + pad (word stride 36)
#define PST2 72                   // P rows: 64 halfs + pad

#define KSTAGE (FKT * KST2 * 2)          // 17408 B
#define VSTAGE (128 * VST2 * 2)          // 18432 B
#define OFF_K  0
#define OFF_V  (2 * KSTAGE)              // 34816
#define OFF_QP (OFF_V + 2 * VSTAGE)      // 71680 (Q then P)
#define OFF_M  (OFF_QP + FQ * QST2 * 2)  // 106496
#define FL_SMEM (OFF_M + 2 * FKT * 4)    // 107008 B

#define SCL 0.12751743f   // (1/sqrt(128)) * log2(e)

__global__ void __launch_bounds__(256, 1)
flash16(const __half* __restrict__ Q, const __half* __restrict__ K,
        const __half* __restrict__ Vt, const float* __restrict__ amask,
        __half* __restrict__ Oc)
{
    extern __shared__ char smc[];
    float* kmb = (float*)(smc + OFF_M);

    const int hb = blockIdx.x;
    const int h = hb & 31, b = hb >> 5;
    const int qb = gridDim.y - 1 - blockIdx.y;     // heavy q-blocks first
    const int q0 = qb * FQ;
    const int tid = threadIdx.x;
    const int w = tid >> 5, lane = tid & 31;
    const int g = lane >> 2, tg = lane & 3;
    const int kvh = h >> 2;
    const int myrowmax = q0 + w * 16 + 15;
    const int w16 = w * 16;

    float oacc[16][4];
#pragma unroll
    for (int nt = 0; nt < 16; nt++)
#pragma unroll
        for (int r = 0; r < 4; r++) oacc[nt][r] = 0.f;
    float m2[2] = {-1e9f, -1e9f}, l2[2] = {0.f, 0.f};

    // loader: K tile [64 keys][128 d], Vt tile [128 d][64 keys], mask
    auto issue = [&](int t, int s) {
        const __half* Kg = K + (size_t)(b * SEQ + t * FKT) * KVW + kvh * HD;
        __half* Ksb = (__half*)(smc + OFF_K + s * KSTAGE);
#pragma unroll
        for (int u = 0; u < 4; u++) {            // 64 rows x 16 chunks
            int i = tid + 256 * u;
            int r = i >> 4, c8 = i & 15;
            uint32_t d = (uint32_t)__cvta_generic_to_shared(
                Ksb + r * KST2 + c8 * 8);
            cp16(d, Kg + (size_t)r * KVW + c8 * 8);
        }
        const __half* Vg = Vt + ((size_t)(b * 8 + kvh) * 128) * SEQ + t * FKT;
        __half* Vsb = (__half*)(smc + OFF_V + s * VSTAGE);
#pragma unroll
        for (int u = 0; u < 4; u++) {            // 128 rows x 8 chunks
            int i = tid + 256 * u;
            int r = i >> 3, c8 = i & 7;
            uint32_t d = (uint32_t)__cvta_generic_to_shared(
                Vsb + r * VST2 + c8 * 8);
            cp16(d, Vg + (size_t)r * SEQ + c8 * 8);
        }
        if (tid < FKT)
            kmb[s * FKT + tid] =
                (amask[b * SEQ + t * FKT + tid] > 0.f) ? 0.f : -1e9f;
        CP_COMMIT();
    };

    issue(0, 0);

    // Q tile -> smem (plain stores): 128 rows x 16 chunks of 8 halfs
    {
        const __half* Qg = Q + (size_t)(b * SEQ + q0) * HID + h * HD;
        __half* Qs = (__half*)(smc + OFF_QP);
#pragma unroll
        for (int u = 0; u < 8; u++) {
            int i = tid + 256 * u;
            int r = i >> 4, c8 = i & 15;
            float4 v = *(const float4*)(Qg + (size_t)r * HID + c8 * 8);
            *(float4*)(Qs + r * QST2 + c8 * 8) = v;
        }
    }
    __syncthreads();

    // Q fragments -> registers (32 regs)
    uint32_t qa[8][4];
    {
        const uint32_t* Qw = (const uint32_t*)(smc + OFF_QP);
#pragma unroll
        for (int ks = 0; ks < 8; ks++) {
            const int kw = ks * 8;
            qa[ks][0] = Qw[(w16 + g) * 68 + kw + tg];
            qa[ks][1] = Qw[(w16 + g + 8) * 68 + kw + tg];
            qa[ks][2] = Qw[(w16 + g) * 68 + kw + 4 + tg];
            qa[ks][3] = Qw[(w16 + g + 8) * 68 + kw + 4 + tg];
        }
    }
    __syncthreads();   // Q reads done -> region becomes P

    const int T = 2 * (qb + 1);

    for (int t = 0; t < T; t++) {
        const int buf = t & 1;
        if (t + 1 < T) {
            issue(t + 1, buf ^ 1);
            CP_WAIT1();
        } else {
            CP_WAIT0();
        }
        __syncthreads();                         // tile t visible everywhere

        const int k0 = t * FKT;
        if (k0 <= myrowmax) {                    // else fully masked for warp

            // ---- S = Q @ K^T (16 x 64 per warp) ----
            float sacc[8][4];
#pragma unroll
            for (int nt = 0; nt < 8; nt++)
#pragma unroll
                for (int r = 0; r < 4; r++) sacc[nt][r] = 0.f;

            const uint32_t* Kw = (const uint32_t*)(smc + OFF_K + buf * KSTAGE);
#pragma unroll
            for (int ks = 0; ks < 8; ks++) {
                const int kw = ks * 8;
#pragma unroll
                for (int nt = 0; nt < 8; nt++) {
                    uint32_t b0 = Kw[(nt * 8 + g) * 68 + kw + tg];
                    uint32_t b1 = Kw[(nt * 8 + g) * 68 + kw + 4 + tg];
                    mma_f16(sacc[nt], qa[ks][0], qa[ks][1], qa[ks][2],
                            qa[ks][3], b0, b1);
                }
            }

            // ---- mask + scale into exp2 domain ----
            const int rowg0 = q0 + w16 + g;
            const int rowg1 = rowg0 + 8;
#pragma unroll
            for (int nt = 0; nt < 8; nt++) {
                int cl = nt * 8 + 2 * tg;
                int c0 = k0 + cl;
                float kb0 = kmb[buf * FKT + cl];
                float kb1 = kmb[buf * FKT + cl + 1];
                sacc[nt][0] = (c0     <= rowg0) ? sacc[nt][0] * SCL + kb0 : -1e9f;
                sacc[nt][1] = (c0 + 1 <= rowg0) ? sacc[nt][1] * SCL + kb1 : -1e9f;
                sacc[nt][2] = (c0     <= rowg1) ? sacc[nt][2] * SCL + kb0 : -1e9f;
                sacc[nt][3] = (c0 + 1 <= rowg1) ? sacc[nt][3] * SCL + kb1 : -1e9f;
            }

            // ---- online softmax (exp2 domain), P -> fp16 smem ----
            __half2* Ph = (__half2*)(smc + OFF_QP);
#pragma unroll
            for (int r = 0; r < 2; r++) {
                float pm = -1e30f;
#pragma unroll
                for (int nt = 0; nt < 8; nt++)
                    pm = fmaxf(pm, fmaxf(sacc[nt][2 * r], sacc[nt][2 * r + 1]));
                pm = fmaxf(pm, __shfl_xor_sync(0xffffffffu, pm, 1));
                pm = fmaxf(pm, __shfl_xor_sync(0xffffffffu, pm, 2));
                float mn = fmaxf(m2[r], pm);
                float al = exp2p(m2[r] - mn);
                m2[r] = mn;
                float rs = 0.f;
                __half2* prow = Ph + (w16 + g + 8 * r) * 36;
#pragma unroll
                for (int nt = 0; nt < 8; nt++) {
                    float p0 = exp2p(sacc[nt][2 * r] - mn);
                    float p1 = exp2p(sacc[nt][2 * r + 1] - mn);
                    rs += p0 + p1;
                    prow[nt * 4 + tg] = __floats2half2_rn(p0, p1);
                }
                rs += __shfl_xor_sync(0xffffffffu, rs, 1);
                rs += __shfl_xor_sync(0xffffffffu, rs, 2);
                l2[r] = l2[r] * al + rs;
                if (al != 1.f) {
#pragma unroll
                    for (int nt = 0; nt < 16; nt++) {
                        oacc[nt][2 * r]     *= al;
                        oacc[nt][2 * r + 1] *= al;
                    }
                }
            }
            __syncwarp();

            // ---- O += P @ V (contract over keys; B = Vt[d][key]) ----
            const uint32_t* Pw = (const uint32_t*)(smc + OFF_QP);
            const uint32_t* Vw = (const uint32_t*)(smc + OFF_V + buf * VSTAGE);
#pragma unroll
            for (int ks = 0; ks < 4; ks++) {
                const int kw = ks * 8;
                uint32_t a0 = Pw[(w16 + g) * 36 + kw + tg];
                uint32_t a1 = Pw[(w16 + g + 8) * 36 + kw + tg];
                uint32_t a2 = Pw[(w16 + g) * 36 + kw + 4 + tg];
                uint32_t a3 = Pw[(w16 + g + 8) * 36 + kw + 4 + tg];
#pragma unroll
                for (int nt = 0; nt < 16; nt++) {
                    uint32_t b0 = Vw[(nt * 8 + g) * 36 + kw + tg];
                    uint32_t b1 = Vw[(nt * 8 + g) * 36 + kw + 4 + tg];
                    mma_f16(oacc[nt], a0, a1, a2, a3, b0, b1);
                }
            }
        }
        __syncthreads();                         // all reads of buf done
    }

    // ---- epilogue: normalize + fp16 store to A ----
    float i0 = 1.f / l2[0], i1 = 1.f / l2[1];
    __half* Ar0 = Oc + (size_t)(b * SEQ + q0 + w16 + g) * HID + h * HD;
    __half* Ar1 = Ar0 + (size_t)8 * HID;
#pragma unroll
    for (int nt = 0; nt < 16; nt++) {
        int c = nt * 8 + 2 * tg;
        *(__half2*)(Ar0 + c) = __floats2half2_rn(oacc[nt][0] * i0,
                                                 oacc[nt][1] * i0);
        *(__half2*)(Ar1 + c) = __floats2half2_rn(oacc[nt][2] * i1,
                                                 oacc[nt][3] * i1);
    }
}

// ---------------------------------------------------------------------------
// Launch
// ---------------------------------------------------------------------------
extern "C" void kernel_launch(void* const* d_in, const int* in_sizes, int n_in,
                              void* d_out, int out_size)
{
    const float* hs    = (const float*)d_in[0];
    const float* amask = (const float*)d_in[1];
    const int*   pos   = (const int*)d_in[2];
    const float* Wq    = (const float*)d_in[3];
    const float* Wk    = (const float*)d_in[4];
    const float* Wv    = (const float*)d_in[5];
    const float* Wo    = (const float*)d_in[6];
    float* out = (float*)d_out;

    __half *Xp, *Wqp, *Wkp, *Wvp, *Wop, *Qp, *Kp, *Vp, *Vtp, *Ap;
    cudaGetSymbolAddress((void**)&Xp,  g_X);
    cudaGetSymbolAddress((void**)&Wqp, g_Wq);
    cudaGetSymbolAddress((void**)&Wkp, g_Wk);
    cudaGetSymbolAddress((void**)&Wvp, g_Wv);
    cudaGetSymbolAddress((void**)&Wop, g_Wo);
    cudaGetSymbolAddress((void**)&Qp,  g_Q);
    cudaGetSymbolAddress((void**)&Kp,  g_K);
    cudaGetSymbolAddress((void**)&Vp,  g_V);
    cudaGetSymbolAddress((void**)&Vtp, g_Vt);
    cudaGetSymbolAddress((void**)&Ap,  g_A);

    cudaFuncSetAttribute(gemm16, cudaFuncAttributeMaxDynamicSharedMemorySize,
                         GEMM_SMEM);
    cudaFuncSetAttribute(flash16, cudaFuncAttributeMaxDynamicSharedMemorySize,
                         FL_SMEM);

    // Convert X to fp16; transpose+convert weights to [N][K] fp16
    {
        int n = MROWS * HID / 4;
        f2h_kernel<<<(n + 255) / 256, 256>>>(hs, Xp, n);
        dim3 blk(32, 8);
        transpose_h<<<dim3(HID / 32, HID / 32), blk>>>(Wq, Wqp, HID, HID);
        transpose_h<<<dim3(KVW / 32, HID / 32), blk>>>(Wk, Wkp, HID, KVW);
        transpose_h<<<dim3(KVW / 32, HID / 32), blk>>>(Wv, Wvp, HID, KVW);
        transpose_h<<<dim3(HID / 32, HID / 32), blk>>>(Wo, Wop, HID, HID);
    }

    // Projections (fp16 tensor cores, fp32 accumulate), fp16 outputs
    gemm16<<<dim3(HID / BN, MROWS / BM), 128, GEMM_SMEM>>>(Xp, Wqp, Qp, MROWS, HID, HID, 1);
    gemm16<<<dim3(KVW / BN, MROWS / BM), 128, GEMM_SMEM>>>(Xp, Wkp, Kp, MROWS, KVW, HID, 1);
    gemm16<<<dim3(KVW / BN, MROWS / BM), 128, GEMM_SMEM>>>(Xp, Wvp, Vp, MROWS, KVW, HID, 1);

    // RoPE on Q and K (fp16 in-place)
    {
        int npq = MROWS * (HID / 2);
        rope_h<<<(npq + 255) / 256, 256>>>(Qp, pos, HID, npq);
        int npk = MROWS * (KVW / 2);
        rope_h<<<(npk + 255) / 256, 256>>>(Kp, pos, KVW, npk);
    }

    // Transpose V for the PV matmul
    {
        dim3 blk(32, 8);
        vtrans_kernel<<<dim3(SEQ / 32, 128 / 32, 16), blk>>>(Vp, Vtp);
    }

    // FP16 tensor-core flash attention
    flash16<<<dim3(NHEADS * BATCH, SEQ / FQ), 256, FL_SMEM>>>(Qp, Kp, Vtp,
                                                              amask, Ap);

    // Output projection, fp32 output
    gemm16<<<dim3(HID / BN, MROWS / BM), 128, GEMM_SMEM>>>(Ap, Wop, out, MROWS, HID, HID, 0);
}

// round 11
// speedup vs baseline: 1.7573x; 1.0171x over previous
#include <cuda_runtime.h>
#include <cuda_fp16.h>
#include <math.h>
#include <stdint.h>

// ---------------------------------------------------------------------------
// Problem constants
// ---------------------------------------------------------------------------
#define HID    4096
#define SEQ    2048
#define BATCH  2
#define NHEADS 32
#define NKV    8
#define HD     128
#define KVW    (NKV * HD)        // 1024
#define MROWS  (BATCH * SEQ)     // 4096
#define NQKV   (HID + 2 * KVW)   // 6144

// ---------------------------------------------------------------------------
// Scratch (device globals: no allocation allowed) — fp16 operands
// ---------------------------------------------------------------------------
__device__ __half g_X   [(size_t)MROWS * HID];
__device__ __half g_Wqkv[(size_t)NQKV * HID];   // [n][k], rows 0..4095=Wq^T, 4096..5119=Wk^T, 5120..6143=Wv^T
__device__ __half g_Wo  [(size_t)HID * HID];    // transposed [N][K]
__device__ __half g_Q   [(size_t)MROWS * HID];
__device__ __half g_K   [(size_t)MROWS * KVW];
__device__ __half g_V   [(size_t)MROWS * KVW];
__device__ __half g_Vt  [(size_t)MROWS * KVW];  // [b*8+kvh][d][seq]
__device__ __half g_A   [(size_t)MROWS * HID];

// ---------------------------------------------------------------------------
// helpers
// ---------------------------------------------------------------------------
__global__ void f2h_kernel(const float* __restrict__ in,
                           __half* __restrict__ out, int n4)
{
    int i = blockIdx.x * blockDim.x + threadIdx.x;
    if (i >= n4) return;
    float4 v = ((const float4*)in)[i];
    __half2* o = (__half2*)(out + 4 * (size_t)i);
    o[0] = __floats2half2_rn(v.x, v.y);
    o[1] = __floats2half2_rn(v.z, v.w);
}

// transpose + convert: out[n][k] = half(in[k][n])
__global__ void transpose_h(const float* __restrict__ in,
                            __half* __restrict__ out, int K, int N)
{
    __shared__ float t[32][33];
    int k0 = blockIdx.y * 32, n0 = blockIdx.x * 32;
    int x = threadIdx.x, y = threadIdx.y;   // 32 x 8
#pragma unroll
    for (int i = 0; i < 32; i += 8)
        t[y + i][x] = in[(size_t)(k0 + y + i) * N + n0 + x];
    __syncthreads();
#pragma unroll
    for (int i = 0; i < 32; i += 8)
        out[(size_t)(n0 + y + i) * K + k0 + x] = __float2half_rn(t[x][y + i]);
}

// V transpose: Vt[b*8+kvh][d][s] = V[(b*SEQ+s)][kvh*128+d]
__global__ void vtrans_kernel(const __half* __restrict__ V,
                              __half* __restrict__ Vt)
{
    __shared__ __half t[32][33];
    int p = blockIdx.z;
    int b = p >> 3, kvh = p & 7;
    int s0 = blockIdx.x * 32, d0 = blockIdx.y * 32;
    int x = threadIdx.x, y = threadIdx.y;
#pragma unroll
    for (int i = 0; i < 32; i += 8)
        t[y + i][x] = V[(size_t)(b * SEQ + s0 + y + i) * KVW + kvh * 128 + d0 + x];
    __syncthreads();
#pragma unroll
    for (int i = 0; i < 32; i += 8)
        Vt[((size_t)p * 128 + d0 + y + i) * SEQ + s0 + x] = t[x][y + i];
}

// fast exp2 on the fma/alu pipes
__device__ __forceinline__ float exp2p(float x) {
    x = fmaxf(x, -126.f);
    float t = x + 12582912.f;
    float n = t - 12582912.f;
    float f = x - n;
    float p = 1.5403530e-4f;
    p = fmaf(p, f, 1.3333558e-3f);
    p = fmaf(p, f, 9.6181291e-3f);
    p = fmaf(p, f, 5.5504109e-2f);
    p = fmaf(p, f, 2.4022651e-1f);
    p = fmaf(p, f, 6.9314718e-1f);
    p = fmaf(p, f, 1.0f);
    float sc = __int_as_float(0x3f800000 + (__float_as_int(t) << 23));
    return p * sc;
}

__device__ __forceinline__ void mma_f16(float* c, uint32_t a0, uint32_t a1,
                                        uint32_t a2, uint32_t a3,
                                        uint32_t b0, uint32_t b1)
{
    asm volatile(
        "mma.sync.aligned.m16n8k16.row.col.f32.f16.f16.f32 "
        "{%0,%1,%2,%3}, {%4,%5,%6,%7}, {%8,%9}, {%0,%1,%2,%3};\n"
        : "+f"(c[0]), "+f"(c[1]), "+f"(c[2]), "+f"(c[3])
        : "r"(a0), "r"(a1), "r"(a2), "r"(a3), "r"(b0), "r"(b1));
}

__device__ __forceinline__ void ldsm4(uint32_t* r, uint32_t addr) {
    asm volatile("ldmatrix.sync.aligned.m8n8.x4.shared.b16 {%0,%1,%2,%3}, [%4];"
                 : "=r"(r[0]), "=r"(r[1]), "=r"(r[2]), "=r"(r[3]) : "r"(addr));
}

__device__ __forceinline__ void cp16(uint32_t dst, const void* src) {
    asm volatile("cp.async.cg.shared.global [%0], [%1], 16;\n"
                 :: "r"(dst), "l"(src));
}
#define CP_COMMIT() asm volatile("cp.async.commit_group;\n" ::: "memory")
#define CP_WAIT1()  asm volatile("cp.async.wait_group 1;\n" ::: "memory")
#define CP_WAIT0()  asm volatile("cp.async.wait_group 0;\n" ::: "memory")

// ldmatrix per-lane offset patterns (halfs), row-stride supplied by caller.
// A-pattern (x4 tiles: m0k0, m8k0, m0k8, m8k8):
//   arow = (l&7) + ((l>>3)&1)*8 ;  akh = (l>>4)*8
// B-pattern (x4 tiles: n0k0, n0k8, n8k0, n8k8):
//   brow = (l&7) + (l>>4)*8    ;  bkh = ((l>>3)&1)*8

// ---------------------------------------------------------------------------
// FP16 tensor-core GEMM body: 128x128x64 tile, 128 threads (2x2 warps),
// 2 CTAs/SM, 2-stage cp.async, ldmatrix fragment loads.
// ---------------------------------------------------------------------------
#define BM 128
#define BN 128
#define BK 64
#define GST2 72                        // halfs per smem row (144 B)
#define GSTAGE (BM * GST2 * 2)         // bytes per tile stage
#define GEMM_SMEM (4 * GSTAGE)         // 73728 B

// fused QKV: Bt = Wqkv [6144][4096]; output split by column block
__global__ void __launch_bounds__(128, 2)
gemm16qkv(const __half* __restrict__ A, const __half* __restrict__ Bt,
          __half* __restrict__ Cq, __half* __restrict__ Ck,
          __half* __restrict__ Cv)
{
    extern __shared__ char smc[];
    const int tid  = threadIdx.x;
    const int warp = tid >> 5;
    const int lane = tid & 31;
    const int wm = warp >> 1;
    const int wn = warp & 1;
    const int g  = lane >> 2;
    const int tg = lane & 3;
    const int bm = blockIdx.y * BM;
    const int bn = blockIdx.x * BN;
    const int K = HID;

    const uint32_t sA = (uint32_t)__cvta_generic_to_shared(smc);
    const uint32_t sB = sA + 2 * GSTAGE;
    const uint32_t aoff = ((((lane & 7) + ((lane >> 3) & 1) * 8)) * GST2 +
                           (lane >> 4) * 8) * 2;
    const uint32_t boff = ((((lane & 7) + (lane >> 4) * 8)) * GST2 +
                           ((lane >> 3) & 1) * 8) * 2;

    float acc[4][8][4];
#pragma unroll
    for (int mi = 0; mi < 4; mi++)
#pragma unroll
        for (int ni = 0; ni < 8; ni++)
#pragma unroll
            for (int r = 0; r < 4; r++) acc[mi][ni][r] = 0.f;

    const int T = K / BK;

    auto issue = [&](int t, int s) {
        const __half* Ag = A + (size_t)bm * K + t * BK;
#pragma unroll
        for (int u = 0; u < 8; u++) {
            int i = tid + 128 * u;
            int r = i >> 3, c8 = i & 7;
            cp16(sA + s * GSTAGE + (r * GST2 + c8 * 8) * 2,
                 Ag + (size_t)r * K + c8 * 8);
        }
        const __half* Bg = Bt + (size_t)bn * K + t * BK;
#pragma unroll
        for (int u = 0; u < 8; u++) {
            int i = tid + 128 * u;
            int r = i >> 3, c8 = i & 7;
            cp16(sB + s * GSTAGE + (r * GST2 + c8 * 8) * 2,
                 Bg + (size_t)r * K + c8 * 8);
        }
        CP_COMMIT();
    };

    issue(0, 0);

    int buf = 0;
    for (int t = 0; t < T; t++) {
        if (t + 1 < T) {
            issue(t + 1, buf ^ 1);
            CP_WAIT1();
        } else {
            CP_WAIT0();
        }
        __syncthreads();

        const uint32_t Ab = sA + buf * GSTAGE;
        const uint32_t Bb = sB + buf * GSTAGE;

#pragma unroll
        for (int ks = 0; ks < 4; ks++) {
            uint32_t a[4][4], b[4][4];
#pragma unroll
            for (int mi = 0; mi < 4; mi++)
                ldsm4(a[mi], Ab + ((wm * 64 + mi * 16) * GST2 + ks * 16) * 2 + aoff);
#pragma unroll
            for (int ni2 = 0; ni2 < 4; ni2++)
                ldsm4(b[ni2], Bb + ((wn * 64 + ni2 * 16) * GST2 + ks * 16) * 2 + boff);
#pragma unroll
            for (int mi = 0; mi < 4; mi++)
#pragma unroll
                for (int ni = 0; ni < 8; ni++)
                    mma_f16(acc[mi][ni], a[mi][0], a[mi][1], a[mi][2], a[mi][3],
                            b[ni >> 1][(ni & 1) * 2], b[ni >> 1][(ni & 1) * 2 + 1]);
        }
        __syncthreads();
        buf ^= 1;
    }

    // epilogue: route to Q/K/V by column block, fp16 output
    __half* Co; int Nout; int colb;
    if (bn < HID)             { Co = Cq; Nout = HID; colb = bn; }
    else if (bn < HID + KVW)  { Co = Ck; Nout = KVW; colb = bn - HID; }
    else                      { Co = Cv; Nout = KVW; colb = bn - HID - KVW; }

#pragma unroll
    for (int mi = 0; mi < 4; mi++) {
        int row0 = bm + wm * 64 + mi * 16 + g;
#pragma unroll
        for (int ni = 0; ni < 8; ni++) {
            int col = colb + wn * 64 + ni * 8 + tg * 2;
            *(__half2*)(Co + (size_t)row0 * Nout + col) =
                __floats2half2_rn(acc[mi][ni][0], acc[mi][ni][1]);
            *(__half2*)(Co + (size_t)(row0 + 8) * Nout + col) =
                __floats2half2_rn(acc[mi][ni][2], acc[mi][ni][3]);
        }
    }
}

// generic fp32-output GEMM (Wo projection)
__global__ void __launch_bounds__(128, 2)
gemm16f(const __half* __restrict__ A, const __half* __restrict__ Bt,
        float* __restrict__ C, int M, int N, int K)
{
    extern __shared__ char smc[];
    const int tid  = threadIdx.x;
    const int warp = tid >> 5;
    const int lane = tid & 31;
    const int wm = warp >> 1;
    const int wn = warp & 1;
    const int g  = lane >> 2;
    const int tg = lane & 3;
    const int bm = blockIdx.y * BM;
    const int bn = blockIdx.x * BN;

    const uint32_t sA = (uint32_t)__cvta_generic_to_shared(smc);
    const uint32_t sB = sA + 2 * GSTAGE;
    const uint32_t aoff = ((((lane & 7) + ((lane >> 3) & 1) * 8)) * GST2 +
                           (lane >> 4) * 8) * 2;
    const uint32_t boff = ((((lane & 7) + (lane >> 4) * 8)) * GST2 +
                           ((lane >> 3) & 1) * 8) * 2;

    float acc[4][8][4];
#pragma unroll
    for (int mi = 0; mi < 4; mi++)
#pragma unroll
        for (int ni = 0; ni < 8; ni++)
#pragma unroll
            for (int r = 0; r < 4; r++) acc[mi][ni][r] = 0.f;

    const int T = K / BK;

    auto issue = [&](int t, int s) {
        const __half* Ag = A + (size_t)bm * K + t * BK;
#pragma unroll
        for (int u = 0; u < 8; u++) {
            int i = tid + 128 * u;
            int r = i >> 3, c8 = i & 7;
            cp16(sA + s * GSTAGE + (r * GST2 + c8 * 8) * 2,
                 Ag + (size_t)r * K + c8 * 8);
        }
        const __half* Bg = Bt + (size_t)bn * K + t * BK;
#pragma unroll
        for (int u = 0; u < 8; u++) {
            int i = tid + 128 * u;
            int r = i >> 3, c8 = i & 7;
            cp16(sB + s * GSTAGE + (r * GST2 + c8 * 8) * 2,
                 Bg + (size_t)r * K + c8 * 8);
        }
        CP_COMMIT();
    };

    issue(0, 0);

    int buf = 0;
    for (int t = 0; t < T; t++) {
        if (t + 1 < T) {
            issue(t + 1, buf ^ 1);
            CP_WAIT1();
        } else {
            CP_WAIT0();
        }
        __syncthreads();

        const uint32_t Ab = sA + buf * GSTAGE;
        const uint32_t Bb = sB + buf * GSTAGE;

#pragma unroll
        for (int ks = 0; ks < 4; ks++) {
            uint32_t a[4][4], b[4][4];
#pragma unroll
            for (int mi = 0; mi < 4; mi++)
                ldsm4(a[mi], Ab + ((wm * 64 + mi * 16) * GST2 + ks * 16) * 2 + aoff);
#pragma unroll
            for (int ni2 = 0; ni2 < 4; ni2++)
                ldsm4(b[ni2], Bb + ((wn * 64 + ni2 * 16) * GST2 + ks * 16) * 2 + boff);
#pragma unroll
            for (int mi = 0; mi < 4; mi++)
#pragma unroll
                for (int ni = 0; ni < 8; ni++)
                    mma_f16(acc[mi][ni], a[mi][0], a[mi][1], a[mi][2], a[mi][3],
                            b[ni >> 1][(ni & 1) * 2], b[ni >> 1][(ni & 1) * 2 + 1]);
        }
        __syncthreads();
        buf ^= 1;
    }

#pragma unroll
    for (int mi = 0; mi < 4; mi++) {
        int row0 = bm + wm * 64 + mi * 16 + g;
#pragma unroll
        for (int ni = 0; ni < 8; ni++) {
            int col = bn + wn * 64 + ni * 8 + tg * 2;
            *(float2*)(C + (size_t)row0 * N + col) =
                make_float2(acc[mi][ni][0], acc[mi][ni][1]);
            *(float2*)(C + (size_t)(row0 + 8) * N + col) =
                make_float2(acc[mi][ni][2], acc[mi][ni][3]);
        }
    }
}

// ---------------------------------------------------------------------------
// RoPE (in-place on fp16, pair-safe).
// ---------------------------------------------------------------------------
__global__ void rope_h(__half* __restrict__ T, const int* __restrict__ pos_ids,
                       int cols, int npairs)
{
    int idx = blockIdx.x * blockDim.x + threadIdx.x;
    if (idx >= npairs) return;
    int half_ = cols >> 1;
    int row = idx / half_;
    int cp = idx - row * half_;
    int h = cp >> 6;
    int d = cp & 63;
    int c0 = h * 128 + d;
    float pos = (float)pos_ids[row];
    double inv = pow(10000.0, -((double)d) / 64.0);
    float ang = (float)((double)pos * inv);
    float sn = sinf(ang), cs = cosf(ang);
    __half* rowp = T + (size_t)row * cols;
    float x0 = __half2float(rowp[c0]);
    float x1 = __half2float(rowp[c0 + 64]);
    rowp[c0]      = __float2half_rn(x0 * cs - x1 * sn);
    rowp[c0 + 64] = __float2half_rn(x1 * cs + x0 * sn);
}

// ---------------------------------------------------------------------------
// FP16 tensor-core flash attention (causal, GQA), ldmatrix fragment loads.
// CTA = 128 q rows x head x batch; 8 warps x 16 rows; K-tile 64, 2-stage.
// ---------------------------------------------------------------------------
#define FQ   128
#define FKT  64
#define QST2 136
#define KST2 136
#define VST2 72
#define PST2 72

#define KSTAGE (FKT * KST2 * 2)
#define VSTAGE (128 * VST2 * 2)
#define OFF_K  0
#define OFF_V  (2 * KSTAGE)
#define OFF_QP (OFF_V + 2 * VSTAGE)
#define OFF_M  (OFF_QP + FQ * QST2 * 2)
#define FL_SMEM (OFF_M + 2 * FKT * 4)    // 107008 B

#define SCL 0.12751743f   // (1/sqrt(128)) * log2(e)

__global__ void __launch_bounds__(256, 1)
flash16(const __half* __restrict__ Q, const __half* __restrict__ K,
        const __half* __restrict__ Vt, const float* __restrict__ amask,
        __half* __restrict__ Oc)
{
    extern __shared__ char smc[];
    float* kmb = (float*)(smc + OFF_M);
    const uint32_t sbase = (uint32_t)__cvta_generic_to_shared(smc);

    const int hb = blockIdx.x;
    const int h = hb & 31, b = hb >> 5;
    const int qb = gridDim.y - 1 - blockIdx.y;
    const int q0 = qb * FQ;
    const int tid = threadIdx.x;
    const int w = tid >> 5, lane = tid & 31;
    const int g = lane >> 2, tg = lane & 3;
    const int kvh = h >> 2;
    const int myrowmax = q0 + w * 16 + 15;
    const int w16 = w * 16;

    const uint32_t aoffP = ((((lane & 7) + ((lane >> 3) & 1) * 8)) * PST2 +
                            (lane >> 4) * 8) * 2;
    const uint32_t boffK = ((((lane & 7) + (lane >> 4) * 8)) * KST2 +
                            ((lane >> 3) & 1) * 8) * 2;
    const uint32_t boffV = ((((lane & 7) + (lane >> 4) * 8)) * VST2 +
                            ((lane >> 3) & 1) * 8) * 2;

    float oacc[16][4];
#pragma unroll
    for (int nt = 0; nt < 16; nt++)
#pragma unroll
        for (int r = 0; r < 4; r++) oacc[nt][r] = 0.f;
    float m2[2] = {-1e9f, -1e9f}, l2[2] = {0.f, 0.f};

    auto issue = [&](int t, int s) {
        const __half* Kg = K + (size_t)(b * SEQ + t * FKT) * KVW + kvh * HD;
        uint32_t Ksb = sbase + OFF_K + s * KSTAGE;
#pragma unroll
        for (int u = 0; u < 4; u++) {
            int i = tid + 256 * u;
            int r = i >> 4, c8 = i & 15;
            cp16(Ksb + (r * KST2 + c8 * 8) * 2, Kg + (size_t)r * KVW + c8 * 8);
        }
        const __half* Vg = Vt + ((size_t)(b * 8 + kvh) * 128) * SEQ + t * FKT;
        uint32_t Vsb = sbase + OFF_V + s * VSTAGE;
#pragma unroll
        for (int u = 0; u < 4; u++) {
            int i = tid + 256 * u;
            int r = i >> 3, c8 = i & 7;
            cp16(Vsb + (r * VST2 + c8 * 8) * 2, Vg + (size_t)r * SEQ + c8 * 8);
        }
        if (tid < FKT)
            kmb[s * FKT + tid] =
                (amask[b * SEQ + t * FKT + tid] > 0.f) ? 0.f : -1e9f;
        CP_COMMIT();
    };

    issue(0, 0);

    // Q tile -> smem
    {
        const __half* Qg = Q + (size_t)(b * SEQ + q0) * HID + h * HD;
        __half* Qs = (__half*)(smc + OFF_QP);
#pragma unroll
        for (int u = 0; u < 8; u++) {
            int i = tid + 256 * u;
            int r = i >> 4, c8 = i & 15;
            float4 v = *(const float4*)(Qg + (size_t)r * HID + c8 * 8);
            *(float4*)(Qs + r * QST2 + c8 * 8) = v;
        }
    }
    __syncthreads();

    // Q fragments -> registers (32 regs)
    uint32_t qa[8][4];
    {
        const uint32_t* Qw = (const uint32_t*)(smc + OFF_QP);
#pragma unroll
        for (int ks = 0; ks < 8; ks++) {
            const int kw = ks * 8;
            qa[ks][0] = Qw[(w16 + g) * 68 + kw + tg];
            qa[ks][1] = Qw[(w16 + g + 8) * 68 + kw + tg];
            qa[ks][2] = Qw[(w16 + g) * 68 + kw + 4 + tg];
            qa[ks][3] = Qw[(w16 + g + 8) * 68 + kw + 4 + tg];
        }
    }
    __syncthreads();   // Q reads done -> region becomes P

    const int T = 2 * (qb + 1);
    const uint32_t Pbase = sbase + OFF_QP + (w16 * PST2) * 2;

    for (int t = 0; t < T; t++) {
        const int buf = t & 1;
        if (t + 1 < T) {
            issue(t + 1, buf ^ 1);
            CP_WAIT1();
        } else {
            CP_WAIT0();
        }
        __syncthreads();

        const int k0 = t * FKT;
        if (k0 <= myrowmax) {

            // ---- S = Q @ K^T (16 x 64 per warp) ----
            float sacc[8][4];
#pragma unroll
            for (int nt = 0; nt < 8; nt++)
#pragma unroll
                for (int r = 0; r < 4; r++) sacc[nt][r] = 0.f;

            const uint32_t Kb = sbase + OFF_K + buf * KSTAGE;
#pragma unroll
            for (int ks = 0; ks < 8; ks++) {
#pragma unroll
                for (int nt2 = 0; nt2 < 4; nt2++) {
                    uint32_t kb[4];
                    ldsm4(kb, Kb + (nt2 * 16 * KST2 + ks * 16) * 2 + boffK);
                    mma_f16(sacc[nt2 * 2], qa[ks][0], qa[ks][1], qa[ks][2],
                            qa[ks][3], kb[0], kb[1]);
                    mma_f16(sacc[nt2 * 2 + 1], qa[ks][0], qa[ks][1], qa[ks][2],
                            qa[ks][3], kb[2], kb[3]);
                }
            }

            // ---- mask + scale into exp2 domain ----
            const int rowg0 = q0 + w16 + g;
            const int rowg1 = rowg0 + 8;
#pragma unroll
            for (int nt = 0; nt < 8; nt++) {
                int cl = nt * 8 + 2 * tg;
                int c0 = k0 + cl;
                float kb0 = kmb[buf * FKT + cl];
                float kb1 = kmb[buf * FKT + cl + 1];
                sacc[nt][0] = (c0     <= rowg0) ? sacc[nt][0] * SCL + kb0 : -1e9f;
                sacc[nt][1] = (c0 + 1 <= rowg0) ? sacc[nt][1] * SCL + kb1 : -1e9f;
                sacc[nt][2] = (c0     <= rowg1) ? sacc[nt][2] * SCL + kb0 : -1e9f;
                sacc[nt][3] = (c0 + 1 <= rowg1) ? sacc[nt][3] * SCL + kb1 : -1e9f;
            }

            // ---- online softmax (exp2 domain), P -> fp16 smem ----
            __half2* Ph = (__half2*)(smc + OFF_QP);
#pragma unroll
            for (int r = 0; r < 2; r++) {
                float pm = -1e30f;
#pragma unroll
                for (int nt = 0; nt < 8; nt++)
                    pm = fmaxf(pm, fmaxf(sacc[nt][2 * r], sacc[nt][2 * r + 1]));
                pm = fmaxf(pm, __shfl_xor_sync(0xffffffffu, pm, 1));
                pm = fmaxf(pm, __shfl_xor_sync(0xffffffffu, pm, 2));
                float mn = fmaxf(m2[r], pm);
                float al = exp2p(m2[r] - mn);
                m2[r] = mn;
                float rs = 0.f;
                __half2* prow = Ph + (w16 + g + 8 * r) * 36;
#pragma unroll
                for (int nt = 0; nt < 8; nt++) {
                    float p0 = exp2p(sacc[nt][2 * r] - mn);
                    float p1 = exp2p(sacc[nt][2 * r + 1] - mn);
                    rs += p0 + p1;
                    prow[nt * 4 + tg] = __floats2half2_rn(p0, p1);
                }
                rs += __shfl_xor_sync(0xffffffffu, rs, 1);
                rs += __shfl_xor_sync(0xffffffffu, rs, 2);
                l2[r] = l2[r] * al + rs;
                if (al != 1.f) {
#pragma unroll
                    for (int nt = 0; nt < 16; nt++) {
                        oacc[nt][2 * r]     *= al;
                        oacc[nt][2 * r + 1] *= al;
                    }
                }
            }
            __syncwarp();

            // ---- O += P @ V ----
            const uint32_t Vb = sbase + OFF_V + buf * VSTAGE;
#pragma unroll
            for (int ks = 0; ks < 4; ks++) {
                uint32_t pa[4];
                ldsm4(pa, Pbase + (ks * 16) * 2 + aoffP);
#pragma unroll
                for (int nt2 = 0; nt2 < 8; nt2++) {
                    uint32_t vb[4];
                    ldsm4(vb, Vb + (nt2 * 16 * VST2 + ks * 16) * 2 + boffV);
                    mma_f16(oacc[nt2 * 2], pa[0], pa[1], pa[2], pa[3],
                            vb[0], vb[1]);
                    mma_f16(oacc[nt2 * 2 + 1], pa[0], pa[1], pa[2], pa[3],
                            vb[2], vb[3]);
                }
            }
        }
        __syncthreads();
    }

    // ---- epilogue: normalize + fp16 store to A ----
    float i0 = 1.f / l2[0], i1 = 1.f / l2[1];
    __half* Ar0 = Oc + (size_t)(b * SEQ + q0 + w16 + g) * HID + h * HD;
    __half* Ar1 = Ar0 + (size_t)8 * HID;
#pragma unroll
    for (int nt = 0; nt < 16; nt++) {
        int c = nt * 8 + 2 * tg;
        *(__half2*)(Ar0 + c) = __floats2half2_rn(oacc[nt][0] * i0,
                                                 oacc[nt][1] * i0);
        *(__half2*)(Ar1 + c) = __floats2half2_rn(oacc[nt][2] * i1,
                                                 oacc[nt][3] * i1);
    }
}

// ---------------------------------------------------------------------------
// Launch
// ---------------------------------------------------------------------------
extern "C" void kernel_launch(void* const* d_in, const int* in_sizes, int n_in,
                              void* d_out, int out_size)
{
    const float* hs    = (const float*)d_in[0];
    const float* amask = (const float*)d_in[1];
    const int*   pos   = (const int*)d_in[2];
    const float* Wq    = (const float*)d_in[3];
    const float* Wk    = (const float*)d_in[4];
    const float* Wv    = (const float*)d_in[5];
    const float* Wo    = (const float*)d_in[6];
    float* out = (float*)d_out;

    __half *Xp, *Wqkvp, *Wop, *Qp, *Kp, *Vp, *Vtp, *Ap;
    cudaGetSymbolAddress((void**)&Xp,    g_X);
    cudaGetSymbolAddress((void**)&Wqkvp, g_Wqkv);
    cudaGetSymbolAddress((void**)&Wop,   g_Wo);
    cudaGetSymbolAddress((void**)&Qp,    g_Q);
    cudaGetSymbolAddress((void**)&Kp,    g_K);
    cudaGetSymbolAddress((void**)&Vp,    g_V);
    cudaGetSymbolAddress((void**)&Vtp,   g_Vt);
    cudaGetSymbolAddress((void**)&Ap,    g_A);

    cudaFuncSetAttribute(gemm16qkv, cudaFuncAttributeMaxDynamicSharedMemorySize,
                         GEMM_SMEM);
    cudaFuncSetAttribute(gemm16f, cudaFuncAttributeMaxDynamicSharedMemorySize,
                         GEMM_SMEM);
    cudaFuncSetAttribute(flash16, cudaFuncAttributeMaxDynamicSharedMemorySize,
                         FL_SMEM);

    // Convert X; transpose+convert weights (QKV concatenated rows)
    {
        int n = MROWS * HID / 4;
        f2h_kernel<<<(n + 255) / 256, 256>>>(hs, Xp, n);
        dim3 blk(32, 8);
        transpose_h<<<dim3(HID / 32, HID / 32), blk>>>(Wq, Wqkvp, HID, HID);
        transpose_h<<<dim3(KVW / 32, HID / 32), blk>>>(Wk, Wqkvp + (size_t)HID * HID, HID, KVW);
        transpose_h<<<dim3(KVW / 32, HID / 32), blk>>>(Wv, Wqkvp + (size_t)(HID + KVW) * HID, HID, KVW);
        transpose_h<<<dim3(HID / 32, HID / 32), blk>>>(Wo, Wop, HID, HID);
    }

    // Fused QKV projection (fp16 tensor cores, fp32 accumulate)
    gemm16qkv<<<dim3(NQKV / BN, MROWS / BM), 128, GEMM_SMEM>>>(Xp, Wqkvp,
                                                               Qp, Kp, Vp);

    // RoPE on Q and K (fp16 in-place)
    {
        int npq = MROWS * (HID / 2);
        rope_h<<<(npq + 255) / 256, 256>>>(Qp, pos, HID, npq);
        int npk = MROWS * (KVW / 2);
        rope_h<<<(npk + 255) / 256, 256>>>(Kp, pos, KVW, npk);
    }

    // Transpose V for the PV matmul
    {
        dim3 blk(32, 8);
        vtrans_kernel<<<dim3(SEQ / 32, 128 / 32, 16), blk>>>(Vp, Vtp);
    }

    // FP16 tensor-core flash attention
    flash16<<<dim3(NHEADS * BATCH, SEQ / FQ), 256, FL_SMEM>>>(Qp, Kp, Vtp,
                                                              amask, Ap);

    // Output projection, fp32 output
    gemm16f<<<dim3(HID / BN, MROWS / BM), 128, GEMM_SMEM>>>(Ap, Wop, out,
                                                            MROWS, HID, HID);
}